// round 1
// baseline (speedup 1.0000x reference)
#include <cuda_runtime.h>

// GraphConvolution on GB300:
//   Wu = sum_{c<=r} u_weight[c]; Wv likewise          (k_prep)
//   su = u @ Wu ; sv = v @ Wv                          (k_feat)
//   top = deg[:nu] * (adj @ sv); bot = deg[nu:] * (adjT @ su)   (k_gemm, split-K partials)
//   out = concat(top,bot) + bias                       (k_final)

#define IN_DIM 128
#define HID    64
#define NMAX   8192
#define SPLITS 4

__device__ float g_Wu[IN_DIM * HID];
__device__ float g_Wv[IN_DIM * HID];
__device__ float g_su[NMAX * HID];
__device__ float g_sv[NMAX * HID];
// partial sums: [2 gemms][SPLITS][NMAX][HID]  (deterministic split-K, no atomics)
__device__ float g_part[2 * SPLITS * NMAX * HID];

// ---------------------------------------------------------------------------
__global__ void k_prep(const float* __restrict__ uw, const float* __restrict__ vw,
                       const int* __restrict__ rp) {
    const int r = rp[0];  // static rating-class count - 1 (read on device; no host sync allowed)
    const int n = IN_DIM * HID;
    for (int i = blockIdx.x * blockDim.x + threadIdx.x; i < n; i += gridDim.x * blockDim.x) {
        float a = 0.f, b = 0.f;
        for (int c = 0; c <= r; c++) { a += uw[c * n + i]; b += vw[c * n + i]; }
        g_Wu[i] = a; g_Wv[i] = b;
    }
}

// ---------------------------------------------------------------------------
// su / sv:  X[rows,128] @ W[128,64].  32 rows per CTA, W + row-tile in SMEM.
__global__ __launch_bounds__(256)
void k_feat(const float* __restrict__ u, const float* __restrict__ v, int nu, int nv) {
    __shared__ float Ws[IN_DIM * HID];   // 32 KB
    __shared__ float Us[32 * IN_DIM];    // 16 KB
    const float* X; const float* W; float* out; int rows;
    if (blockIdx.y == 0) { X = u; W = g_Wu; out = g_su; rows = nu; }
    else                 { X = v; W = g_Wv; out = g_sv; rows = nv; }

    const int tid = threadIdx.x;
    const int r0  = blockIdx.x * 32;
    if (r0 >= rows) return;  // whole block, uniform

    for (int i = tid; i < IN_DIM * HID; i += 256) Ws[i] = W[i];
    for (int i = tid; i < 32 * IN_DIM; i += 256)  Us[i] = X[(size_t)r0 * IN_DIM + i];
    __syncthreads();

    const int h = tid & 63;
    for (int rl = tid >> 6; rl < 32; rl += 4) {
        float acc = 0.f;
        #pragma unroll
        for (int k = 0; k < IN_DIM; k += 4) {
            float4 uq = *(const float4*)&Us[rl * IN_DIM + k];
            acc += uq.x * Ws[(k + 0) * HID + h];
            acc += uq.y * Ws[(k + 1) * HID + h];
            acc += uq.z * Ws[(k + 2) * HID + h];
            acc += uq.w * Ws[(k + 3) * HID + h];
        }
        out[(size_t)(r0 + rl) * HID + h] = acc;
    }
}

// ---------------------------------------------------------------------------
// Big GEMM pair (one kernel, blockIdx.z selects orientation).
//   gz=0: C[m,h] = sum_k adj[m*nv + k]  * sv[k,h]   (m in [0,nu), k in [0,nv))
//   gz=1: C[m,h] = sum_k adj[k*nv + m]  * su[k,h]   (m in [0,nv), k in [0,nu))
// Tile: BM=128, BN=64(=HID), BK=16; 256 threads, each 8x4 micro-tile.
// Split-K over blockIdx.y -> g_part (deterministic).
__global__ __launch_bounds__(256)
void k_gemm(const float* __restrict__ adj, int nu, int nv) {
    const int gz = blockIdx.z;
    const int K  = gz ? nu : nv;
    const float* __restrict__ B = gz ? g_su : g_sv;

    const int m0     = blockIdx.x * 128;
    const int klen   = K / SPLITS;
    const int k0     = blockIdx.y * klen;
    const int ntiles = klen / 16;

    __shared__ float As[16][132];  // [k][m], pad 132 -> 2-way max store conflict, 16B-aligned rows
    __shared__ float Bs[16][64];   // [k][h]

    const int tid = threadIdx.x;
    const int mb  = (tid >> 4) << 3;  // micro-tile m base (0..120)
    const int nb  = (tid & 15) << 2;  // micro-tile n base (0..60)

    float acc[8][4];
    #pragma unroll
    for (int i = 0; i < 8; i++)
        #pragma unroll
        for (int j = 0; j < 4; j++) acc[i][j] = 0.f;

    // loader lane mapping
    const int bk = tid >> 4;          // Bs row   0..15
    const int bc = (tid & 15) << 2;   // Bs col4
    const int am = tid >> 2;          // gz=0: adj row within tile 0..63 (and +64)
    const int ac = (tid & 3) << 2;    // gz=0: k col4 within tile
    const int ak = tid >> 5;          // gz=1: adj(k) row within tile 0..7 (and +8)
    const int aq = (tid & 31) << 2;   // gz=1: m col4 within tile

    float4 pa0, pa1, pb;

    auto load_regs = [&](int kt) {
        const int kbase = k0 + kt * 16;
        pb = *(const float4*)&B[(size_t)(kbase + bk) * HID + bc];
        if (gz == 0) {
            pa0 = *(const float4*)&adj[(size_t)(m0 + am)      * nv + kbase + ac];
            pa1 = *(const float4*)&adj[(size_t)(m0 + am + 64) * nv + kbase + ac];
        } else {
            pa0 = *(const float4*)&adj[(size_t)(kbase + ak)     * nv + m0 + aq];
            pa1 = *(const float4*)&adj[(size_t)(kbase + ak + 8) * nv + m0 + aq];
        }
    };
    auto store_smem = [&]() {
        *(float4*)&Bs[bk][bc] = pb;
        if (gz == 0) {  // transpose into As[k][m]
            As[ac + 0][am] = pa0.x; As[ac + 1][am] = pa0.y;
            As[ac + 2][am] = pa0.z; As[ac + 3][am] = pa0.w;
            As[ac + 0][am + 64] = pa1.x; As[ac + 1][am + 64] = pa1.y;
            As[ac + 2][am + 64] = pa1.z; As[ac + 3][am + 64] = pa1.w;
        } else {        // already [k][m]
            *(float4*)&As[ak][aq]     = pa0;
            *(float4*)&As[ak + 8][aq] = pa1;
        }
    };

    load_regs(0);
    store_smem();
    __syncthreads();

    for (int kt = 0; kt < ntiles; kt++) {
        const bool more = (kt + 1 < ntiles);
        if (more) load_regs(kt + 1);  // global prefetch overlaps FFMA below

        #pragma unroll
        for (int k = 0; k < 16; k++) {
            float4 a0 = *(const float4*)&As[k][mb];
            float4 a1 = *(const float4*)&As[k][mb + 4];
            float4 b4 = *(const float4*)&Bs[k][nb];
            float a[8] = {a0.x, a0.y, a0.z, a0.w, a1.x, a1.y, a1.z, a1.w};
            float bb[4] = {b4.x, b4.y, b4.z, b4.w};
            #pragma unroll
            for (int i = 0; i < 8; i++)
                #pragma unroll
                for (int j = 0; j < 4; j++) acc[i][j] += a[i] * bb[j];
        }
        __syncthreads();
        if (more) { store_smem(); __syncthreads(); }
    }

    float* __restrict__ P = &g_part[(size_t)((gz * SPLITS + blockIdx.y) * NMAX) * HID];
    #pragma unroll
    for (int i = 0; i < 8; i++) {
        float4 o = make_float4(acc[i][0], acc[i][1], acc[i][2], acc[i][3]);
        *(float4*)&P[(size_t)(m0 + mb + i) * HID + nb] = o;
    }
}

// ---------------------------------------------------------------------------
__global__ void k_final(const float* __restrict__ degree, const float* __restrict__ bias,
                        float* __restrict__ out, int nu, int nv) {
    const int total = (nu + nv) * HID;
    const int idx = blockIdx.x * blockDim.x + threadIdx.x;
    if (idx >= total) return;
    const int row = idx >> 6;
    const int h   = idx & 63;
    const int g   = (row < nu) ? 0 : 1;
    const int rr  = g ? (row - nu) : row;
    float s = 0.f;
    #pragma unroll
    for (int sp = 0; sp < SPLITS; sp++)
        s += g_part[((size_t)(g * SPLITS + sp) * NMAX + rr) * HID + h];
    out[idx] = degree[row] * s + bias[h];
}

// ---------------------------------------------------------------------------
extern "C" void kernel_launch(void* const* d_in, const int* in_sizes, int n_in,
                              void* d_out, int out_size) {
    const float* u      = (const float*)d_in[0];
    const float* v      = (const float*)d_in[1];
    const float* adj    = (const float*)d_in[2];
    const float* degree = (const float*)d_in[3];
    const float* uw     = (const float*)d_in[4];
    const float* vw     = (const float*)d_in[5];
    const float* bias   = (const float*)d_in[6];
    const int*   rp     = (const int*)d_in[7];

    const int nu = in_sizes[0] / IN_DIM;   // 8192
    const int nv = in_sizes[1] / IN_DIM;   // 8192
    float* out = (float*)d_out;

    k_prep<<<16, 256>>>(uw, vw, rp);

    dim3 gf(nu / 32, 2);
    k_feat<<<gf, 256>>>(u, v, nu, nv);

    dim3 gg(nu / 128, SPLITS, 2);
    k_gemm<<<gg, 256>>>(adj, nu, nv);

    const int total = (nu + nv) * HID;
    k_final<<<(total + 255) / 256, 256>>>(degree, bias, out, nu, nv);
}

// round 2
// speedup vs baseline: 1.4971x; 1.4971x over previous
#include <cuda_runtime.h>
#include <cstdint>

// GraphConvolution on GB300:
//   Wu = sum_{c<=r} u_weight[c]; Wv likewise          (k_prep)
//   su = u @ Wu ; sv = v @ Wv                          (k_feat, fp32 FFMA - tiny)
//   top = deg[:nu] * (adj @ sv); bot = deg[nu:] * (adjT @ su)   (k_gemm, tf32 mma.sync, split-K)
//   out = concat(top,bot) + bias                       (k_final)

#define IN_DIM 128
#define HID    64
#define NMAX   8192
#define SPLITS 4

__device__ float g_Wu[IN_DIM * HID];
__device__ float g_Wv[IN_DIM * HID];
__device__ float g_su[NMAX * HID];
__device__ float g_sv[NMAX * HID];
// partial sums: [2 gemms][SPLITS][NMAX][HID]  (deterministic split-K, no atomics)
__device__ float g_part[2 * SPLITS * NMAX * HID];

__device__ __forceinline__ float to_tf32(float x) {
    asm("cvt.rna.tf32.f32 %0, %0;" : "+f"(x));
    return x;
}

// ---------------------------------------------------------------------------
__global__ void k_prep(const float* __restrict__ uw, const float* __restrict__ vw,
                       const int* __restrict__ rp) {
    const int r = rp[0];
    const int n = IN_DIM * HID;
    for (int i = blockIdx.x * blockDim.x + threadIdx.x; i < n; i += gridDim.x * blockDim.x) {
        float a = 0.f, b = 0.f;
        for (int c = 0; c <= r; c++) { a += uw[c * n + i]; b += vw[c * n + i]; }
        g_Wu[i] = a; g_Wv[i] = b;
    }
}

// ---------------------------------------------------------------------------
// su / sv:  X[rows,128] @ W[128,64].  32 rows per CTA, W + row-tile in SMEM.
__global__ __launch_bounds__(256)
void k_feat(const float* __restrict__ u, const float* __restrict__ v, int nu, int nv) {
    __shared__ float Ws[IN_DIM * HID];
    __shared__ float Us[32 * IN_DIM];
    const float* X; const float* W; float* out; int rows;
    if (blockIdx.y == 0) { X = u; W = g_Wu; out = g_su; rows = nu; }
    else                 { X = v; W = g_Wv; out = g_sv; rows = nv; }

    const int tid = threadIdx.x;
    const int r0  = blockIdx.x * 32;
    if (r0 >= rows) return;

    for (int i = tid; i < IN_DIM * HID; i += 256) Ws[i] = W[i];
    for (int i = tid; i < 32 * IN_DIM; i += 256)  Us[i] = X[(size_t)r0 * IN_DIM + i];
    __syncthreads();

    const int h = tid & 63;
    for (int rl = tid >> 6; rl < 32; rl += 4) {
        float acc = 0.f;
        #pragma unroll
        for (int k = 0; k < IN_DIM; k += 4) {
            float4 uq = *(const float4*)&Us[rl * IN_DIM + k];
            acc += uq.x * Ws[(k + 0) * HID + h];
            acc += uq.y * Ws[(k + 1) * HID + h];
            acc += uq.z * Ws[(k + 2) * HID + h];
            acc += uq.w * Ws[(k + 3) * HID + h];
        }
        out[(size_t)(r0 + rl) * HID + h] = acc;
    }
}

// ---------------------------------------------------------------------------
// Big GEMM pair via tf32 mma.sync.m16n8k8 (row.col).
//   gz=0: C[m,h] = sum_k adj[m*nv + k]  * sv[k,h]
//   gz=1: C[m,h] = sum_k adj[k*nv + m]  * su[k,h]
// CTA tile: BM=128, BN=64, BK=16. 8 warps as 4(M)x2(N) -> each warp 32x32.
// SMEM As[k][m] (pad 132), Bs[k][h] (pad 68) hold tf32-rounded values.
// Split-K over blockIdx.y -> g_part (deterministic).
__global__ __launch_bounds__(256)
void k_gemm(const float* __restrict__ adj, int nu, int nv) {
    const int gz = blockIdx.z;
    const int K  = gz ? nu : nv;
    const float* __restrict__ B = gz ? g_su : g_sv;

    const int m0     = blockIdx.x * 128;
    const int klen   = K / SPLITS;
    const int k0     = blockIdx.y * klen;
    const int ntiles = klen / 16;

    __shared__ float As[16][132];  // [k][m]
    __shared__ float Bs[16][68];   // [k][h]  (pad 68 -> frag loads <=2-way conflict)

    const int tid  = threadIdx.x;
    const int warp = tid >> 5;
    const int lane = tid & 31;
    const int g    = lane >> 2;   // groupID
    const int t    = lane & 3;    // thread-in-group
    const int wm   = (warp >> 1) * 32;  // warp m offset in CTA tile
    const int wn   = (warp & 1) * 32;   // warp n offset

    // accumulators: 2 mtiles(16) x 4 ntiles(8) x 4 regs
    float acc[2][4][4];
    #pragma unroll
    for (int i = 0; i < 2; i++)
        #pragma unroll
        for (int j = 0; j < 4; j++)
            #pragma unroll
            for (int q = 0; q < 4; q++) acc[i][j][q] = 0.f;

    // loader lane mapping (global -> regs -> SMEM, with tf32 round at store)
    const int bk = tid >> 4;          // Bs row 0..15
    const int bc = (tid & 15) << 2;   // Bs col4
    const int am = tid >> 2;          // gz=0: adj row within tile 0..63 (and +64)
    const int ac = (tid & 3) << 2;    // gz=0: k col4 within tile
    const int ak = tid >> 5;          // gz=1: adj(k) row within tile 0..7 (and +8)
    const int aq = (tid & 31) << 2;   // gz=1: m col4 within tile

    float4 pa0, pa1, pb;

    auto load_regs = [&](int kt) {
        const int kbase = k0 + kt * 16;
        pb = *(const float4*)&B[(size_t)(kbase + bk) * HID + bc];
        if (gz == 0) {
            pa0 = *(const float4*)&adj[(size_t)(m0 + am)      * nv + kbase + ac];
            pa1 = *(const float4*)&adj[(size_t)(m0 + am + 64) * nv + kbase + ac];
        } else {
            pa0 = *(const float4*)&adj[(size_t)(kbase + ak)     * nv + m0 + aq];
            pa1 = *(const float4*)&adj[(size_t)(kbase + ak + 8) * nv + m0 + aq];
        }
    };
    auto store_smem = [&]() {
        Bs[bk][bc + 0] = to_tf32(pb.x); Bs[bk][bc + 1] = to_tf32(pb.y);
        Bs[bk][bc + 2] = to_tf32(pb.z); Bs[bk][bc + 3] = to_tf32(pb.w);
        if (gz == 0) {  // transpose into As[k][m]
            As[ac + 0][am] = to_tf32(pa0.x); As[ac + 1][am] = to_tf32(pa0.y);
            As[ac + 2][am] = to_tf32(pa0.z); As[ac + 3][am] = to_tf32(pa0.w);
            As[ac + 0][am + 64] = to_tf32(pa1.x); As[ac + 1][am + 64] = to_tf32(pa1.y);
            As[ac + 2][am + 64] = to_tf32(pa1.z); As[ac + 3][am + 64] = to_tf32(pa1.w);
        } else {        // already [k][m]
            As[ak][aq + 0]     = to_tf32(pa0.x); As[ak][aq + 1]     = to_tf32(pa0.y);
            As[ak][aq + 2]     = to_tf32(pa0.z); As[ak][aq + 3]     = to_tf32(pa0.w);
            As[ak + 8][aq + 0] = to_tf32(pa1.x); As[ak + 8][aq + 1] = to_tf32(pa1.y);
            As[ak + 8][aq + 2] = to_tf32(pa1.z); As[ak + 8][aq + 3] = to_tf32(pa1.w);
        }
    };

    load_regs(0);
    store_smem();
    __syncthreads();

    for (int kt = 0; kt < ntiles; kt++) {
        const bool more = (kt + 1 < ntiles);
        if (more) load_regs(kt + 1);  // global prefetch overlaps MMA below

        #pragma unroll
        for (int kk = 0; kk < 16; kk += 8) {
            // A fragments: 2 mtiles x 4 regs
            uint32_t af[2][4];
            #pragma unroll
            for (int i = 0; i < 2; i++) {
                const int mb = wm + i * 16;
                af[i][0] = __float_as_uint(As[kk + t][mb + g]);
                af[i][1] = __float_as_uint(As[kk + t][mb + g + 8]);
                af[i][2] = __float_as_uint(As[kk + t + 4][mb + g]);
                af[i][3] = __float_as_uint(As[kk + t + 4][mb + g + 8]);
            }
            // B fragments: 4 ntiles x 2 regs
            uint32_t bf[4][2];
            #pragma unroll
            for (int j = 0; j < 4; j++) {
                const int nb = wn + j * 8;
                bf[j][0] = __float_as_uint(Bs[kk + t][nb + g]);
                bf[j][1] = __float_as_uint(Bs[kk + t + 4][nb + g]);
            }
            #pragma unroll
            for (int i = 0; i < 2; i++)
                #pragma unroll
                for (int j = 0; j < 4; j++) {
                    asm volatile(
                        "mma.sync.aligned.m16n8k8.row.col.f32.tf32.tf32.f32 "
                        "{%0,%1,%2,%3}, {%4,%5,%6,%7}, {%8,%9}, {%0,%1,%2,%3};"
                        : "+f"(acc[i][j][0]), "+f"(acc[i][j][1]),
                          "+f"(acc[i][j][2]), "+f"(acc[i][j][3])
                        : "r"(af[i][0]), "r"(af[i][1]), "r"(af[i][2]), "r"(af[i][3]),
                          "r"(bf[j][0]), "r"(bf[j][1]));
                }
        }
        __syncthreads();
        if (more) { store_smem(); __syncthreads(); }
    }

    float* __restrict__ P = &g_part[(size_t)((gz * SPLITS + blockIdx.y) * NMAX) * HID];
    #pragma unroll
    for (int i = 0; i < 2; i++) {
        #pragma unroll
        for (int j = 0; j < 4; j++) {
            const int m = m0 + wm + i * 16 + g;
            const int n = wn + j * 8 + 2 * t;
            *(float2*)&P[(size_t)m * HID + n]       = make_float2(acc[i][j][0], acc[i][j][1]);
            *(float2*)&P[(size_t)(m + 8) * HID + n] = make_float2(acc[i][j][2], acc[i][j][3]);
        }
    }
}

// ---------------------------------------------------------------------------
__global__ void k_final(const float* __restrict__ degree, const float* __restrict__ bias,
                        float* __restrict__ out, int nu, int nv) {
    const int total = (nu + nv) * HID;
    const int idx = blockIdx.x * blockDim.x + threadIdx.x;
    if (idx >= total) return;
    const int row = idx >> 6;
    const int h   = idx & 63;
    const int gg  = (row < nu) ? 0 : 1;
    const int rr  = gg ? (row - nu) : row;
    float s = 0.f;
    #pragma unroll
    for (int sp = 0; sp < SPLITS; sp++)
        s += g_part[((size_t)(gg * SPLITS + sp) * NMAX + rr) * HID + h];
    out[idx] = degree[row] * s + bias[h];
}

// ---------------------------------------------------------------------------
extern "C" void kernel_launch(void* const* d_in, const int* in_sizes, int n_in,
                              void* d_out, int out_size) {
    const float* u      = (const float*)d_in[0];
    const float* v      = (const float*)d_in[1];
    const float* adj    = (const float*)d_in[2];
    const float* degree = (const float*)d_in[3];
    const float* uw     = (const float*)d_in[4];
    const float* vw     = (const float*)d_in[5];
    const float* bias   = (const float*)d_in[6];
    const int*   rp     = (const int*)d_in[7];

    const int nu = in_sizes[0] / IN_DIM;   // 8192
    const int nv = in_sizes[1] / IN_DIM;   // 8192
    float* out = (float*)d_out;

    k_prep<<<16, 256>>>(uw, vw, rp);

    dim3 gf(nu / 32, 2);
    k_feat<<<gf, 256>>>(u, v, nu, nv);

    dim3 gg(nu / 128, SPLITS, 2);
    k_gemm<<<gg, 256>>>(adj, nu, nv);

    const int total = (nu + nv) * HID;
    k_final<<<(total + 255) / 256, 256>>>(degree, bias, out, nu, nv);
}

// round 4
// speedup vs baseline: 1.8766x; 1.2535x over previous
#include <cuda_runtime.h>
#include <cstdint>

// GraphConvolution on GB300:
//   Wu = sum_{c<=r} u_weight[c]; Wv likewise          (k_prep)
//   su = u @ Wu ; sv = v @ Wv                          (k_feat)
//   top = deg[:nu] * (adj @ sv); bot = deg[nu:] * (adjT @ su)
//        -> k_gemm<GZ>: tf32 mma.sync, 3-stage cp.async pipeline, split-K
//   out = concat(top,bot) + bias                       (k_final)

#define IN_DIM 128
#define HID    64
#define NMAX   8192
#define SPLITS 4
#define STAGES 3

// SMEM strides chosen for conflict-free fragment LDS:
//   A gz=0 layout [m][k], stride 20  (20g+t mod 32 distinct)
//   A gz=1 layout [k][m], stride 136 (8t+g  mod 32 distinct)
//   B       layout [k][h], stride 72  (8t+g  mod 32 distinct)
#define AS0_STRIDE 20
#define AS1_STRIDE 136
#define BS_STRIDE  72
#define AS_FLOATS  2560   // max(128*20, 16*136)
#define BS_FLOATS  (16 * BS_STRIDE)

__device__ __align__(16) float g_Wu[IN_DIM * HID];
__device__ __align__(16) float g_Wv[IN_DIM * HID];
__device__ __align__(16) float g_su[NMAX * HID];
__device__ __align__(16) float g_sv[NMAX * HID];
__device__ __align__(16) float g_part[2 * SPLITS * NMAX * HID];

__device__ __forceinline__ float to_tf32(float x) {
    asm("cvt.rna.tf32.f32 %0, %0;" : "+f"(x));
    return x;
}
__device__ __forceinline__ uint32_t tf32_bits(float x) {
    return __float_as_uint(to_tf32(x));
}
__device__ __forceinline__ void cp16(void* dst_smem, const void* src_gmem) {
    uint32_t d = (uint32_t)__cvta_generic_to_shared(dst_smem);
    asm volatile("cp.async.cg.shared.global [%0], [%1], 16;\n" :: "r"(d), "l"(src_gmem));
}

// ---------------------------------------------------------------------------
__global__ void k_prep(const float* __restrict__ uw, const float* __restrict__ vw,
                       const int* __restrict__ rp) {
    const int r = rp[0];
    const int n = IN_DIM * HID;
    for (int i = blockIdx.x * blockDim.x + threadIdx.x; i < n; i += gridDim.x * blockDim.x) {
        float a = 0.f, b = 0.f;
        for (int c = 0; c <= r; c++) { a += uw[c * n + i]; b += vw[c * n + i]; }
        g_Wu[i] = a; g_Wv[i] = b;
    }
}

// ---------------------------------------------------------------------------
__global__ __launch_bounds__(256)
void k_feat(const float* __restrict__ u, const float* __restrict__ v, int nu, int nv) {
    __shared__ float Ws[IN_DIM * HID];
    __shared__ float Us[32 * IN_DIM];
    const float* X; const float* W; float* out; int rows;
    if (blockIdx.y == 0) { X = u; W = g_Wu; out = g_su; rows = nu; }
    else                 { X = v; W = g_Wv; out = g_sv; rows = nv; }

    const int tid = threadIdx.x;
    const int r0  = blockIdx.x * 32;
    if (r0 >= rows) return;

    for (int i = tid; i < IN_DIM * HID; i += 256) Ws[i] = W[i];
    for (int i = tid; i < 32 * IN_DIM; i += 256)  Us[i] = X[(size_t)r0 * IN_DIM + i];
    __syncthreads();

    const int h = tid & 63;
    for (int rl = tid >> 6; rl < 32; rl += 4) {
        float acc = 0.f;
        #pragma unroll
        for (int k = 0; k < IN_DIM; k += 4) {
            float4 uq = *(const float4*)&Us[rl * IN_DIM + k];
            acc += uq.x * Ws[(k + 0) * HID + h];
            acc += uq.y * Ws[(k + 1) * HID + h];
            acc += uq.z * Ws[(k + 2) * HID + h];
            acc += uq.w * Ws[(k + 3) * HID + h];
        }
        out[(size_t)(r0 + rl) * HID + h] = acc;
    }
}

// ---------------------------------------------------------------------------
// GZ=0: C[m,h] = sum_k adj[m*nv + k]  * sv[k,h]
// GZ=1: C[m,h] = sum_k adj[k*nv + m]  * su[k,h]
// BM=128, BN=64, BK=16; 8 warps as 4(M)x2(N), each warp 32x32 via m16n8k8 tf32.
// 3-stage cp.async pipeline; split-K over blockIdx.y -> g_part.
// IMPORTANT: one commit_group is issued EVERY iteration (empty at the tail) so
// cp.async.wait_group N always binds the compute tile's group — without the
// padding, the FIFO drains at the tail and the last tile computes on
// incomplete SMEM (the round-3 correctness bug).
template <int GZ>
__global__ __launch_bounds__(256)
void k_gemm(const float* __restrict__ adj, int nu, int nv) {
    const int K = GZ ? nu : nv;
    const float* __restrict__ B = GZ ? g_su : g_sv;

    const int m0     = blockIdx.x * 128;
    const int klen   = K / SPLITS;
    const int k0     = blockIdx.y * klen;
    const int ntiles = klen / 16;

    __shared__ __align__(16) float As[STAGES][AS_FLOATS];
    __shared__ __align__(16) float Bs[STAGES][BS_FLOATS];

    const int tid  = threadIdx.x;
    const int warp = tid >> 5;
    const int lane = tid & 31;
    const int g    = lane >> 2;
    const int t    = lane & 3;
    const int wm   = (warp >> 1) * 32;
    const int wn   = (warp & 1) * 32;

    float acc[2][4][4];
    #pragma unroll
    for (int i = 0; i < 2; i++)
        #pragma unroll
        for (int j = 0; j < 4; j++)
            #pragma unroll
            for (int q = 0; q < 4; q++) acc[i][j][q] = 0.f;

    // -------- async copy issue for one k-tile into stage s --------
    auto issue = [&](int s, int kt) {
        const int kbase = k0 + kt * 16;
        {   // B tile: 16 rows x 64 floats, 256 chunks of 16B, 1 per thread
            const int row = tid >> 4, ch = tid & 15;
            cp16(&Bs[s][row * BS_STRIDE + ch * 4],
                 &B[(size_t)(kbase + row) * HID + ch * 4]);
        }
        if (GZ == 0) {  // A tile [m][k]: 128 rows x 16 floats (4 chunks/row), 2 rows per thread
            const int r = tid >> 2, c = tid & 3;
            cp16(&As[s][r * AS0_STRIDE + c * 4],
                 &adj[(size_t)(m0 + r) * nv + kbase + c * 4]);
            cp16(&As[s][(r + 64) * AS0_STRIDE + c * 4],
                 &adj[(size_t)(m0 + r + 64) * nv + kbase + c * 4]);
        } else {        // A tile [k][m]: 16 rows x 128 floats (32 chunks/row), 2 chunks per thread
            const int row = tid >> 4, ch = tid & 15;
            cp16(&As[s][row * AS1_STRIDE + ch * 4],
                 &adj[(size_t)(kbase + row) * nv + m0 + ch * 4]);
            cp16(&As[s][row * AS1_STRIDE + (ch + 16) * 4],
                 &adj[(size_t)(kbase + row) * nv + m0 + (ch + 16) * 4]);
        }
        asm volatile("cp.async.commit_group;\n" ::);
    };

    // -------- prologue: fill STAGES-1 stages --------
    #pragma unroll
    for (int s = 0; s < STAGES - 1; s++) issue(s, s);

    for (int kt = 0; kt < ntiles; kt++) {
        const int s = kt % STAGES;
        asm volatile("cp.async.wait_group %0;\n" :: "n"(STAGES - 2));
        __syncthreads();

        // refill the stage freed at iteration kt-1; at the tail commit an
        // EMPTY group to keep the wait_group FIFO accounting correct.
        const int nk = kt + STAGES - 1;
        if (nk < ntiles) issue(nk % STAGES, nk);
        else             asm volatile("cp.async.commit_group;\n" ::);

        const float* __restrict__ Asb = As[s];
        const float* __restrict__ Bsb = Bs[s];

        #pragma unroll
        for (int kk = 0; kk < 16; kk += 8) {
            uint32_t af[2][4];
            #pragma unroll
            for (int i = 0; i < 2; i++) {
                const int mb = wm + i * 16 + g;
                if (GZ == 0) {
                    af[i][0] = tf32_bits(Asb[(mb)     * AS0_STRIDE + kk + t]);
                    af[i][1] = tf32_bits(Asb[(mb + 8) * AS0_STRIDE + kk + t]);
                    af[i][2] = tf32_bits(Asb[(mb)     * AS0_STRIDE + kk + t + 4]);
                    af[i][3] = tf32_bits(Asb[(mb + 8) * AS0_STRIDE + kk + t + 4]);
                } else {
                    af[i][0] = tf32_bits(Asb[(kk + t)     * AS1_STRIDE + mb]);
                    af[i][1] = tf32_bits(Asb[(kk + t)     * AS1_STRIDE + mb + 8]);
                    af[i][2] = tf32_bits(Asb[(kk + t + 4) * AS1_STRIDE + mb]);
                    af[i][3] = tf32_bits(Asb[(kk + t + 4) * AS1_STRIDE + mb + 8]);
                }
            }
            uint32_t bf[4][2];
            #pragma unroll
            for (int j = 0; j < 4; j++) {
                const int nb = wn + j * 8 + g;
                bf[j][0] = tf32_bits(Bsb[(kk + t)     * BS_STRIDE + nb]);
                bf[j][1] = tf32_bits(Bsb[(kk + t + 4) * BS_STRIDE + nb]);
            }
            #pragma unroll
            for (int i = 0; i < 2; i++)
                #pragma unroll
                for (int j = 0; j < 4; j++) {
                    asm volatile(
                        "mma.sync.aligned.m16n8k8.row.col.f32.tf32.tf32.f32 "
                        "{%0,%1,%2,%3}, {%4,%5,%6,%7}, {%8,%9}, {%0,%1,%2,%3};"
                        : "+f"(acc[i][j][0]), "+f"(acc[i][j][1]),
                          "+f"(acc[i][j][2]), "+f"(acc[i][j][3])
                        : "r"(af[i][0]), "r"(af[i][1]), "r"(af[i][2]), "r"(af[i][3]),
                          "r"(bf[j][0]), "r"(bf[j][1]));
                }
        }
        __syncthreads();
    }

    float* __restrict__ P = &g_part[(size_t)((GZ * SPLITS + blockIdx.y) * NMAX) * HID];
    #pragma unroll
    for (int i = 0; i < 2; i++) {
        #pragma unroll
        for (int j = 0; j < 4; j++) {
            const int m = m0 + wm + i * 16 + g;
            const int n = wn + j * 8 + 2 * t;
            *(float2*)&P[(size_t)m * HID + n]       = make_float2(acc[i][j][0], acc[i][j][1]);
            *(float2*)&P[(size_t)(m + 8) * HID + n] = make_float2(acc[i][j][2], acc[i][j][3]);
        }
    }
}

// ---------------------------------------------------------------------------
__global__ void k_final(const float* __restrict__ degree, const float* __restrict__ bias,
                        float* __restrict__ out, int nu, int nv) {
    const int total = (nu + nv) * HID;
    const int idx = blockIdx.x * blockDim.x + threadIdx.x;
    if (idx >= total) return;
    const int row = idx >> 6;
    const int h   = idx & 63;
    const int gg  = (row < nu) ? 0 : 1;
    const int rr  = gg ? (row - nu) : row;
    float s = 0.f;
    #pragma unroll
    for (int sp = 0; sp < SPLITS; sp++)
        s += g_part[((size_t)(gg * SPLITS + sp) * NMAX + rr) * HID + h];
    out[idx] = degree[row] * s + bias[h];
}

// ---------------------------------------------------------------------------
extern "C" void kernel_launch(void* const* d_in, const int* in_sizes, int n_in,
                              void* d_out, int out_size) {
    const float* u      = (const float*)d_in[0];
    const float* v      = (const float*)d_in[1];
    const float* adj    = (const float*)d_in[2];
    const float* degree = (const float*)d_in[3];
    const float* uw     = (const float*)d_in[4];
    const float* vw     = (const float*)d_in[5];
    const float* bias   = (const float*)d_in[6];
    const int*   rp     = (const int*)d_in[7];

    const int nu = in_sizes[0] / IN_DIM;   // 8192
    const int nv = in_sizes[1] / IN_DIM;   // 8192
    float* out = (float*)d_out;

    k_prep<<<16, 256>>>(uw, vw, rp);

    dim3 gf(nu / 32, 2);
    k_feat<<<gf, 256>>>(u, v, nu, nv);

    dim3 g0(nu / 128, SPLITS);
    k_gemm<0><<<g0, 256>>>(adj, nu, nv);
    dim3 g1(nv / 128, SPLITS);
    k_gemm<1><<<g1, 256>>>(adj, nu, nv);

    const int total = (nu + nv) * HID;
    k_final<<<(total + 255) / 256, 256>>>(degree, bias, out, nu, nv);
}

// round 5
// speedup vs baseline: 2.2483x; 1.1980x over previous
#include <cuda_runtime.h>
#include <cstdint>

// GraphConvolution on GB300:
//   Wu = sum_{c<=r} u_weight[c]; Wv likewise          (k_prep)
//   su = u @ Wu ; sv = v @ Wv                          (k_feat, smem-transposed W)
//   top = deg[:nu] * (adj @ sv); bot = deg[nu:] * (adjT @ su)
//        -> k_gemm: both orientations in ONE launch (blockIdx.z), tf32 mma.sync,
//           3-stage cp.async pipeline, split-K=8
//   out = concat(top,bot) + bias                       (k_final)

#define IN_DIM 128
#define HID    64
#define NMAX   8192
#define SPLITS 8
#define STAGES 3

// SMEM strides chosen for conflict-free fragment LDS:
//   A gz=0 layout [m][k], stride 20  (20g+t mod 32 distinct)
//   A gz=1 layout [k][m], stride 136 (8t+g  mod 32 distinct)
//   B       layout [k][h], stride 72  (8t+g  mod 32 distinct)
#define AS0_STRIDE 20
#define AS1_STRIDE 136
#define BS_STRIDE  72
#define AS_FLOATS  2560   // max(128*20, 16*136)
#define BS_FLOATS  (16 * BS_STRIDE)

__device__ __align__(16) float g_Wu[IN_DIM * HID];
__device__ __align__(16) float g_Wv[IN_DIM * HID];
__device__ __align__(16) float g_su[NMAX * HID];
__device__ __align__(16) float g_sv[NMAX * HID];
__device__ __align__(16) float g_part[2 * SPLITS * NMAX * HID];

__device__ __forceinline__ float to_tf32(float x) {
    asm("cvt.rna.tf32.f32 %0, %0;" : "+f"(x));
    return x;
}
__device__ __forceinline__ uint32_t tf32_bits(float x) {
    return __float_as_uint(to_tf32(x));
}
__device__ __forceinline__ void cp16(void* dst_smem, const void* src_gmem) {
    uint32_t d = (uint32_t)__cvta_generic_to_shared(dst_smem);
    asm volatile("cp.async.cg.shared.global [%0], [%1], 16;\n" :: "r"(d), "l"(src_gmem));
}

// ---------------------------------------------------------------------------
__global__ void k_prep(const float* __restrict__ uw, const float* __restrict__ vw,
                       const int* __restrict__ rp) {
    const int r = rp[0];
    const int n = IN_DIM * HID;
    for (int i = blockIdx.x * blockDim.x + threadIdx.x; i < n; i += gridDim.x * blockDim.x) {
        float a = 0.f, b = 0.f;
        for (int c = 0; c <= r; c++) { a += uw[c * n + i]; b += vw[c * n + i]; }
        g_Wu[i] = a; g_Wv[i] = b;
    }
}

// ---------------------------------------------------------------------------
// su / sv:  X[rows,128] @ W[128,64].  32 rows per CTA.
// W transposed into SMEM as Wt[h][k] (stride 132 -> conflict-free LDS128),
// so the inner loop is all float4: per 4-k step, 1 Wt LDS128 (per h) shared
// across 8 rows + 8 broadcast Us LDS128 + 32 FFMA.
#define WT_STRIDE 132
__global__ __launch_bounds__(256)
void k_feat(const float* __restrict__ u, const float* __restrict__ v, int nu, int nv) {
    __shared__ float Wt[HID * WT_STRIDE];   // [h][k] ~33 KB
    __shared__ float Us[32 * IN_DIM];       // 16 KB
    const float* X; const float* W; float* out; int rows;
    if (blockIdx.y == 0) { X = u; W = g_Wu; out = g_su; rows = nu; }
    else                 { X = v; W = g_Wv; out = g_sv; rows = nv; }

    const int tid = threadIdx.x;
    const int r0  = blockIdx.x * 32;
    if (r0 >= rows) return;

    for (int i = tid; i < IN_DIM * HID; i += 256) {
        const int k = i >> 6, h = i & 63;           // W is [k][h]
        Wt[h * WT_STRIDE + k] = W[i];
    }
    for (int i = tid; i < 32 * IN_DIM; i += 256)  Us[i] = X[(size_t)r0 * IN_DIM + i];
    __syncthreads();

    const int h  = tid & 63;
    const int rg = (tid >> 6) * 8;   // 8 rows per thread
    float acc[8];
    #pragma unroll
    for (int r = 0; r < 8; r++) acc[r] = 0.f;

    #pragma unroll 4
    for (int k = 0; k < IN_DIM; k += 4) {
        const float4 wq = *(const float4*)&Wt[h * WT_STRIDE + k];
        #pragma unroll
        for (int r = 0; r < 8; r++) {
            const float4 uq = *(const float4*)&Us[(rg + r) * IN_DIM + k];
            acc[r] += uq.x * wq.x + uq.y * wq.y + uq.z * wq.z + uq.w * wq.w;
        }
    }
    #pragma unroll
    for (int r = 0; r < 8; r++)
        out[(size_t)(r0 + rg + r) * HID + h] = acc[r];
}

// ---------------------------------------------------------------------------
// gz = blockIdx.z:
//   gz=0: C[m,h] = sum_k adj[m*nv + k]  * sv[k,h]
//   gz=1: C[m,h] = sum_k adj[k*nv + m]  * su[k,h]
// BM=128, BN=64, BK=16; 8 warps as 4(M)x2(N), each warp 32x32 via m16n8k8 tf32.
// 3-stage cp.async pipeline; split-K over blockIdx.y -> g_part.
// One commit_group EVERY iteration (empty at the tail) keeps wait_group
// accounting correct (round-3 bug).
__global__ __launch_bounds__(256)
void k_gemm(const float* __restrict__ adj, int nu, int nv) {
    const int gz = blockIdx.z;
    const int K  = gz ? nu : nv;
    const float* __restrict__ B = gz ? g_su : g_sv;

    const int m0     = blockIdx.x * 128;
    const int klen   = K / SPLITS;
    const int k0     = blockIdx.y * klen;
    const int ntiles = klen / 16;

    __shared__ __align__(16) float As[STAGES][AS_FLOATS];
    __shared__ __align__(16) float Bs[STAGES][BS_FLOATS];

    const int tid  = threadIdx.x;
    const int warp = tid >> 5;
    const int lane = tid & 31;
    const int g    = lane >> 2;
    const int t    = lane & 3;
    const int wm   = (warp >> 1) * 32;
    const int wn   = (warp & 1) * 32;

    float acc[2][4][4];
    #pragma unroll
    for (int i = 0; i < 2; i++)
        #pragma unroll
        for (int j = 0; j < 4; j++)
            #pragma unroll
            for (int q = 0; q < 4; q++) acc[i][j][q] = 0.f;

    auto issue = [&](int s, int kt) {
        const int kbase = k0 + kt * 16;
        {   // B tile: 16 rows x 64 floats
            const int row = tid >> 4, ch = tid & 15;
            cp16(&Bs[s][row * BS_STRIDE + ch * 4],
                 &B[(size_t)(kbase + row) * HID + ch * 4]);
        }
        if (gz == 0) {  // A tile [m][k]
            const int r = tid >> 2, c = tid & 3;
            cp16(&As[s][r * AS0_STRIDE + c * 4],
                 &adj[(size_t)(m0 + r) * nv + kbase + c * 4]);
            cp16(&As[s][(r + 64) * AS0_STRIDE + c * 4],
                 &adj[(size_t)(m0 + r + 64) * nv + kbase + c * 4]);
        } else {        // A tile [k][m]
            const int row = tid >> 4, ch = tid & 15;
            cp16(&As[s][row * AS1_STRIDE + ch * 4],
                 &adj[(size_t)(kbase + row) * nv + m0 + ch * 4]);
            cp16(&As[s][row * AS1_STRIDE + (ch + 16) * 4],
                 &adj[(size_t)(kbase + row) * nv + m0 + (ch + 16) * 4]);
        }
        asm volatile("cp.async.commit_group;\n" ::);
    };

    #pragma unroll
    for (int s = 0; s < STAGES - 1; s++) issue(s, s);

    for (int kt = 0; kt < ntiles; kt++) {
        const int s = kt % STAGES;
        asm volatile("cp.async.wait_group %0;\n" :: "n"(STAGES - 2));
        __syncthreads();

        const int nk = kt + STAGES - 1;
        if (nk < ntiles) issue(nk % STAGES, nk);
        else             asm volatile("cp.async.commit_group;\n" ::);

        const float* __restrict__ Asb = As[s];
        const float* __restrict__ Bsb = Bs[s];

        #pragma unroll
        for (int kk = 0; kk < 16; kk += 8) {
            uint32_t af[2][4];
            #pragma unroll
            for (int i = 0; i < 2; i++) {
                const int mb = wm + i * 16 + g;
                if (gz == 0) {
                    af[i][0] = tf32_bits(Asb[(mb)     * AS0_STRIDE + kk + t]);
                    af[i][1] = tf32_bits(Asb[(mb + 8) * AS0_STRIDE + kk + t]);
                    af[i][2] = tf32_bits(Asb[(mb)     * AS0_STRIDE + kk + t + 4]);
                    af[i][3] = tf32_bits(Asb[(mb + 8) * AS0_STRIDE + kk + t + 4]);
                } else {
                    af[i][0] = tf32_bits(Asb[(kk + t)     * AS1_STRIDE + mb]);
                    af[i][1] = tf32_bits(Asb[(kk + t)     * AS1_STRIDE + mb + 8]);
                    af[i][2] = tf32_bits(Asb[(kk + t + 4) * AS1_STRIDE + mb]);
                    af[i][3] = tf32_bits(Asb[(kk + t + 4) * AS1_STRIDE + mb + 8]);
                }
            }
            uint32_t bf[4][2];
            #pragma unroll
            for (int j = 0; j < 4; j++) {
                const int nb = wn + j * 8 + g;
                bf[j][0] = tf32_bits(Bsb[(kk + t)     * BS_STRIDE + nb]);
                bf[j][1] = tf32_bits(Bsb[(kk + t + 4) * BS_STRIDE + nb]);
            }
            #pragma unroll
            for (int i = 0; i < 2; i++)
                #pragma unroll
                for (int j = 0; j < 4; j++) {
                    asm volatile(
                        "mma.sync.aligned.m16n8k8.row.col.f32.tf32.tf32.f32 "
                        "{%0,%1,%2,%3}, {%4,%5,%6,%7}, {%8,%9}, {%0,%1,%2,%3};"
                        : "+f"(acc[i][j][0]), "+f"(acc[i][j][1]),
                          "+f"(acc[i][j][2]), "+f"(acc[i][j][3])
                        : "r"(af[i][0]), "r"(af[i][1]), "r"(af[i][2]), "r"(af[i][3]),
                          "r"(bf[j][0]), "r"(bf[j][1]));
                }
        }
        __syncthreads();
    }

    float* __restrict__ P = &g_part[(size_t)((gz * SPLITS + blockIdx.y) * NMAX) * HID];
    #pragma unroll
    for (int i = 0; i < 2; i++) {
        #pragma unroll
        for (int j = 0; j < 4; j++) {
            const int m = m0 + wm + i * 16 + g;
            const int n = wn + j * 8 + 2 * t;
            *(float2*)&P[(size_t)m * HID + n]       = make_float2(acc[i][j][0], acc[i][j][1]);
            *(float2*)&P[(size_t)(m + 8) * HID + n] = make_float2(acc[i][j][2], acc[i][j][3]);
        }
    }
}

// ---------------------------------------------------------------------------
__global__ void k_final(const float* __restrict__ degree, const float* __restrict__ bias,
                        float* __restrict__ out, int nu, int nv) {
    const int total = (nu + nv) * HID;
    const int idx = blockIdx.x * blockDim.x + threadIdx.x;
    if (idx >= total) return;
    const int row = idx >> 6;
    const int h   = idx & 63;
    const int gg  = (row < nu) ? 0 : 1;
    const int rr  = gg ? (row - nu) : row;
    float s = 0.f;
    #pragma unroll
    for (int sp = 0; sp < SPLITS; sp++)
        s += g_part[((size_t)(gg * SPLITS + sp) * NMAX + rr) * HID + h];
    out[idx] = degree[row] * s + bias[h];
}

// ---------------------------------------------------------------------------
extern "C" void kernel_launch(void* const* d_in, const int* in_sizes, int n_in,
                              void* d_out, int out_size) {
    const float* u      = (const float*)d_in[0];
    const float* v      = (const float*)d_in[1];
    const float* adj    = (const float*)d_in[2];
    const float* degree = (const float*)d_in[3];
    const float* uw     = (const float*)d_in[4];
    const float* vw     = (const float*)d_in[5];
    const float* bias   = (const float*)d_in[6];
    const int*   rp     = (const int*)d_in[7];

    const int nu = in_sizes[0] / IN_DIM;   // 8192
    const int nv = in_sizes[1] / IN_DIM;   // 8192 (== nu for this problem)
    float* out = (float*)d_out;

    k_prep<<<16, 256>>>(uw, vw, rp);

    dim3 gf(nu / 32, 2);
    k_feat<<<gf, 256>>>(u, v, nu, nv);

    dim3 gg(nu / 128, SPLITS, 2);   // both orientations in one launch
    k_gemm<<<gg, 256>>>(adj, nu, nv);

    const int total = (nu + nv) * HID;
    k_final<<<(total + 255) / 256, 256>>>(degree, bias, out, nu, nv);
}